// round 15
// baseline (speedup 1.0000x reference)
#include <cuda_runtime.h>
#include <cstdint>

// FocalLoss: loss = sum_b mean_a [ w[a] * (1-p)^2 * BCE(clamp(p), t) ]
// inputs [B, A] f32, targets [A, B] i32 (0/1), w [A] f32 -> scalar f32
//
// Persistent double-buffered variant: 740 blocks (5/SM x 148, one wave, no
// wave transitions). Each block loops over ~11 tiles; input tile k+grid is
// prefetched via cp.async into the alternate 20KB buffer WHILE tile k is
// computed (target LDGs in flight concurrently) -> continuous overlapped
// DRAM demand instead of stage/compute alternation that capped DRAM at 75%.
// Fused single-node tail with release-scope wrapping atom.inc.
constexpr int BVAL = 1000000;
constexpr int AVAL = 40;
constexpr float EPSF = 1e-12f;
constexpr int TPB = 128;
constexpr int NTILES = (BVAL + TPB - 1) / TPB;      // 7813 tiles of 128 b
constexpr int GRID = 740;                           // 5 blocks/SM * 148 SM
constexpr int ROW_F4 = AVAL / 4;                    // 10 float4 per row
constexpr int TILE_F4 = TPB * ROW_F4;               // 1280 float4 per tile
constexpr long TOTAL_F4 = (long)BVAL * ROW_F4;      // 10e6

__device__ double g_acc;            // zero at load; reset by last block each launch
__device__ unsigned int g_count;    // zero at load; self-resets via inc-wrap

__device__ __forceinline__ uint32_t smem_u32(const void* p) {
    uint32_t a;
    asm("{ .reg .u64 t; cvta.to.shared.u64 t, %1; cvt.u32.u64 %0, t; }"
        : "=r"(a) : "l"(p));
    return a;
}

__device__ __forceinline__ void stage_tile(
    const float4* __restrict__ in4, float4* buf, int tile, int tid)
{
    long base_f4 = (long)tile * TILE_F4;
    #pragma unroll
    for (int i = 0; i < ROW_F4; i++) {
        int  sidx = tid + i * TPB;
        long gidx = base_f4 + sidx;
        if (gidx < TOTAL_F4) {
            uint32_t dst = smem_u32(&buf[sidx]);
            asm volatile("cp.async.cg.shared.global [%0], [%1], 16;"
                         :: "r"(dst), "l"(in4 + gidx) : "memory");
        } else {
            buf[sidx] = make_float4(0.f, 0.f, 0.f, 0.f);
        }
    }
    asm volatile("cp.async.commit_group;" ::: "memory");
}

__global__ void __launch_bounds__(TPB) focal_fused_kernel(
    const float* __restrict__ inputs,
    const int*   __restrict__ targets,
    const float* __restrict__ w,
    float* __restrict__ out)
{
    __shared__ float4 s4[2][TILE_F4];   // 2 x 20 KB input buffers
    __shared__ float  sw[AVAL];

    int tid = threadIdx.x;
    if (tid < AVAL) sw[tid] = w[tid];

    const float4* in4 = reinterpret_cast<const float4*>(inputs);

    float acc = 0.0f;
    int tile = blockIdx.x;
    int par = 0;

    if (tile < NTILES)
        stage_tile(in4, s4[0], tile, tid);   // prologue prefetch

    while (tile < NTILES) {
        int next = tile + GRID;
        if (next < NTILES)
            stage_tile(in4, s4[par ^ 1], next, tid);   // overlap with compute

        if (next < NTILES)
            asm volatile("cp.async.wait_group 1;" ::: "memory");  // cur done
        else
            asm volatile("cp.async.wait_group 0;" ::: "memory");
        __syncthreads();

        int b = tile * TPB + tid;
        if (b < BVAL) {
            const float4* buf = s4[par];
            #pragma unroll
            for (int a4 = 0; a4 < ROW_F4; a4++) {
                float4 p4 = buf[tid * ROW_F4 + a4];
                float pv[4] = {p4.x, p4.y, p4.z, p4.w};
                #pragma unroll
                for (int j = 0; j < 4; j++) {
                    int a = a4 * 4 + j;
                    int t = __ldcs(targets + (long)a * BVAL + b);  // coalesced
                    float p  = pv[j];
                    float pc = fminf(fmaxf(p, EPSF), 1.0f - EPSF);
                    float arg = t ? pc : (1.0f - pc);  // t is 0/1: one log
                    float bce = -__logf(arg);          // MUFU.LG2
                    float om  = 1.0f - p;              // unclamped p
                    acc = fmaf(sw[a] * om * om, bce, acc);
                }
            }
        }
        __syncthreads();   // all lanes done with s4[par] before it is restaged

        tile = next;
        par ^= 1;
    }

    // warp reduce
    #pragma unroll
    for (int off = 16; off; off >>= 1)
        acc += __shfl_down_sync(0xffffffffu, acc, off);

    __shared__ float warpsum[TPB / 32];
    if ((tid & 31) == 0) warpsum[tid >> 5] = acc;
    __syncthreads();

    if (tid < TPB / 32) {
        float v = warpsum[tid];
        #pragma unroll
        for (int off = (TPB / 64); off; off >>= 1)
            v += __shfl_down_sync(0xfu, v, off);
        if (tid == 0) {
            atomicAdd(&g_acc, (double)v);
            // Release-scope wrapping inc: orders the g_acc add, no L1 flush.
            unsigned int old;
            asm volatile("atom.release.gpu.global.inc.u32 %0, [%1], %2;"
                         : "=r"(old)
                         : "l"(&g_count), "r"((unsigned)(GRID - 1))
                         : "memory");
            if (old == (unsigned)(GRID - 1)) {
                double tot;
                asm volatile("ld.acquire.gpu.global.f64 %0, [%1];"
                             : "=d"(tot) : "l"(&g_acc) : "memory");
                out[0] = (float)(tot * (1.0 / (double)AVAL));
                asm volatile("st.relaxed.gpu.global.f64 [%0], %1;"
                             :: "l"(&g_acc), "d"(0.0) : "memory");
            }
        }
    }
}

extern "C" void kernel_launch(void* const* d_in, const int* in_sizes, int n_in,
                              void* d_out, int out_size)
{
    const float* inputs  = (const float*)d_in[0];   // [B, A]
    const int*   targets = (const int*)  d_in[1];   // [A, B]
    const float* weights = (const float*)d_in[2];   // [A]

    focal_fused_kernel<<<GRID, TPB>>>(inputs, targets, weights, (float*)d_out);
}

// round 16
// speedup vs baseline: 1.1978x; 1.1978x over previous
#include <cuda_runtime.h>
#include <cstdint>

// FocalLoss: loss = sum_b mean_a [ w[a] * (1-p)^2 * BCE(clamp(p), t) ]
// inputs [B, A] f32, targets [A, B] i32 (0/1), w [A] f32 -> scalar f32
//
// FINAL (= R10, measured best 53.7us, DRAM 74.9%):
// - single fused kernel (1 graph node)
// - input slab staged to smem via lane-contiguous cp.async.cg (16B chunks)
// - targets direct coalesced __ldcs (streaming)
// - t in {0,1} -> exactly one MUFU.LG2 per element (stays HBM-bound)
// - block partial via atomicAdd(double); completion via RELEASE-scope
//   wrapping atom.inc (no __threadfence -> no CCTL.IVALL L1 flush, which
//   was the R2 fusion regression); counter wraps at GRID-1 so every graph
//   replay is deterministic; last block acquire-loads g_acc, writes out,
//   resets g_acc.
// Session evidence: DRAM pinned at ~75% across occupancy 24-52%, TPB
// 128/256, TMA-bulk / per-thread / direct staging, target staging,
// persistent double-buffered scheduling -> the residual gap is DRAM-side
// for this dual-stream pattern; this configuration is the measured optimum.
constexpr int BVAL = 1000000;
constexpr int AVAL = 40;
constexpr float EPSF = 1e-12f;
constexpr int TPB = 256;
constexpr int GRID = (BVAL + TPB - 1) / TPB;        // 3907
constexpr int ROW_F4 = AVAL / 4;                    // 10 float4 per row
constexpr int TILE_F4 = TPB * ROW_F4;               // 2560 float4 per block
constexpr long TOTAL_F4 = (long)BVAL * ROW_F4;      // 10e6

__device__ double g_acc;            // zero at load; reset by last block each launch
__device__ unsigned int g_count;    // zero at load; self-resets via inc-wrap

__device__ __forceinline__ uint32_t smem_u32(const void* p) {
    uint32_t a;
    asm("{ .reg .u64 t; cvta.to.shared.u64 t, %1; cvt.u32.u64 %0, t; }"
        : "=r"(a) : "l"(p));
    return a;
}

__global__ void __launch_bounds__(TPB) focal_fused_kernel(
    const float* __restrict__ inputs,
    const int*   __restrict__ targets,
    const float* __restrict__ w,
    float* __restrict__ out)
{
    __shared__ float4 s4[TILE_F4];     // 40 KB: block's 256 input rows
    __shared__ float  sw[AVAL];

    int tid = threadIdx.x;
    if (tid < AVAL) sw[tid] = w[tid];

    // Stage the block's input slab: lane-contiguous 16B async copies.
    long base_f4 = (long)blockIdx.x * TILE_F4;
    const float4* in4 = reinterpret_cast<const float4*>(inputs);
    #pragma unroll
    for (int i = 0; i < ROW_F4; i++) {
        int  sidx = tid + i * TPB;
        long gidx = base_f4 + sidx;
        if (gidx < TOTAL_F4) {
            uint32_t dst = smem_u32(&s4[sidx]);
            asm volatile("cp.async.cg.shared.global [%0], [%1], 16;"
                         :: "r"(dst), "l"(in4 + gidx) : "memory");
        } else {
            s4[sidx] = make_float4(0.f, 0.f, 0.f, 0.f);
        }
    }
    asm volatile("cp.async.commit_group;" ::: "memory");
    asm volatile("cp.async.wait_group 0;" ::: "memory");
    __syncthreads();

    int b = blockIdx.x * TPB + tid;
    float acc = 0.0f;
    if (b < BVAL) {
        #pragma unroll
        for (int a4 = 0; a4 < ROW_F4; a4++) {
            float4 p4 = s4[tid * ROW_F4 + a4];          // own row from smem
            float pv[4] = {p4.x, p4.y, p4.z, p4.w};
            #pragma unroll
            for (int j = 0; j < 4; j++) {
                int a = a4 * 4 + j;
                int t = __ldcs(targets + (long)a * BVAL + b);  // coalesced per a
                float p  = pv[j];
                float pc = fminf(fmaxf(p, EPSF), 1.0f - EPSF);
                float arg = t ? pc : (1.0f - pc);   // t is 0/1: one log suffices
                float bce = -__logf(arg);           // MUFU.LG2 path
                float om  = 1.0f - p;               // focal weight uses UNCLAMPED p
                acc = fmaf(sw[a] * om * om, bce, acc);
            }
        }
    }

    // warp reduce
    #pragma unroll
    for (int off = 16; off; off >>= 1)
        acc += __shfl_down_sync(0xffffffffu, acc, off);

    __shared__ float warpsum[TPB / 32];
    if ((tid & 31) == 0) warpsum[tid >> 5] = acc;
    __syncthreads();

    if (tid < TPB / 32) {
        float v = warpsum[tid];
        #pragma unroll
        for (int off = (TPB / 64); off; off >>= 1)
            v += __shfl_down_sync(0xffu, v, off);
        if (tid == 0) {
            atomicAdd(&g_acc, (double)v);
            // Release-scope wrapping inc: orders the g_acc add, no L1 flush.
            // Wraps to 0 at GRID-1 -> deterministic across graph replays.
            unsigned int old;
            asm volatile("atom.release.gpu.global.inc.u32 %0, [%1], %2;"
                         : "=r"(old)
                         : "l"(&g_count), "r"((unsigned)(GRID - 1))
                         : "memory");
            if (old == (unsigned)(GRID - 1)) {
                // Last block: all 3907 release-incs done -> all adds visible.
                double tot;
                asm volatile("ld.acquire.gpu.global.f64 %0, [%1];"
                             : "=d"(tot) : "l"(&g_acc) : "memory");
                out[0] = (float)(tot * (1.0 / (double)AVAL));
                asm volatile("st.relaxed.gpu.global.f64 [%0], %1;"
                             :: "l"(&g_acc), "d"(0.0) : "memory");
            }
        }
    }
}

extern "C" void kernel_launch(void* const* d_in, const int* in_sizes, int n_in,
                              void* d_out, int out_size)
{
    const float* inputs  = (const float*)d_in[0];   // [B, A]
    const int*   targets = (const int*)  d_in[1];   // [A, B]
    const float* weights = (const float*)d_in[2];   // [A]

    focal_fused_kernel<<<GRID, TPB>>>(inputs, targets, weights, (float*)d_out);
}